// round 1
// baseline (speedup 1.0000x reference)
#include <cuda_runtime.h>
#include <cuda_bf16.h>
#include <cstddef>

// GodelToposEngine: next = clamp(R @ prev, 0, 1), up to 20 steps.
// status: 1=PROVEN (next==prev), 2=GODEL (next==pprev, step>=2), 3=TIMEOUT.
// allclose: |a-b| <= atol + rtol*|b|, atol=1e-4, rtol=1e-5 (b = second arg).

#define NN 8192
#define MAXS 20
#define ATOL 1e-4f
#define RTOL 1e-5f

// Triple-buffered state vectors + control scalars (no allocation allowed).
__device__ float g_buf[3][NN];
__device__ int g_status;
__device__ int g_steps;
__device__ int g_final;   // which buffer holds the final state
__device__ int g_viol1;   // any element violates allclose(next, prev)
__device__ int g_viol2;   // any element violates allclose(next, pprev)

__global__ void __launch_bounds__(256) init_kernel(const float* __restrict__ sv) {
    int idx = blockIdx.x * 256 + threadIdx.x;   // grid 32x256 = 8192
    float v = sv[idx];
    g_buf[0][idx] = v;   // prev  for step 1
    g_buf[2][idx] = v;   // pprev for step 1
    if (idx == 0) {
        g_status = 0;
        g_steps = 0;
        g_final = 2;     // default (unused unless something odd happens)
        g_viol1 = 0;
        g_viol2 = 0;
    }
}

// One step: GEMV + clamp + convergence-violation flags.
// 1024 blocks x 256 threads; warp-per-row (8 rows per block).
__global__ void __launch_bounds__(256) gemv_step(const float* __restrict__ R,
                                                 int pi, int ppi, int ni) {
    if (g_status != 0) return;   // frozen: skip all work

    __shared__ float4 xs[NN / 4];   // 32 KB: prev vector
    __shared__ int sv1, sv2;

    const int tid = threadIdx.x;
    if (tid == 0) { sv1 = 0; sv2 = 0; }

    const float4* pv = (const float4*)g_buf[pi];
#pragma unroll
    for (int i = 0; i < NN / 4 / 256; i++)
        xs[tid + 256 * i] = pv[tid + 256 * i];
    __syncthreads();

    const int warp = tid >> 5;
    const int lane = tid & 31;
    const int row  = blockIdx.x * 8 + warp;

    const float4* rp = (const float4*)(R + (size_t)row * NN);

    float s0 = 0.f, s1 = 0.f, s2 = 0.f, s3 = 0.f;
#pragma unroll 8
    for (int j = lane; j < NN / 4; j += 32) {
        float4 a = rp[j];
        float4 b = xs[j];
        s0 += a.x * b.x;
        s1 += a.y * b.y;
        s2 += a.z * b.z;
        s3 += a.w * b.w;
    }
    float s = (s0 + s1) + (s2 + s3);
#pragma unroll
    for (int o = 16; o; o >>= 1) s += __shfl_xor_sync(0xFFFFFFFFu, s, o);

    if (lane == 0) {
        float v = fminf(fmaxf(s, 0.0f), 1.0f);
        g_buf[ni][row] = v;
        float p  = g_buf[pi][row];
        float pp = g_buf[ppi][row];
        if (fabsf(v - p)  > ATOL + RTOL * fabsf(p))  atomicOr(&sv1, 1);
        if (fabsf(v - pp) > ATOL + RTOL * fabsf(pp)) atomicOr(&sv2, 1);
    }
    __syncthreads();
    if (tid == 0) {
        if (sv1) atomicOr(&g_viol1, 1);
        if (sv2) atomicOr(&g_viol2, 1);
    }
}

// Per-step status update (frozen-carry semantics of the reference scan).
__global__ void update_step(int k, int ni) {
    if (g_status == 0) {
        g_steps = k;          // steps tracks the last active step
        g_final = ni;         // prev <- next happened this step
        if (g_viol1 == 0)                     g_status = 1;  // PROVEN (priority)
        else if (k >= 2 && g_viol2 == 0)      g_status = 2;  // GODEL
    }
    g_viol1 = 0;
    g_viol2 = 0;
}

__global__ void __launch_bounds__(256) final_kernel(float* __restrict__ out,
                                                    int out_size) {
    int idx = blockIdx.x * 256 + threadIdx.x;   // grid 32x256 = 8192
    int fi = g_final;
    if (idx < NN && idx < out_size) out[idx] = g_buf[fi][idx];
    if (idx == 0 && out_size >= NN + 2) {
        int st = g_status;
        out[NN]     = (float)(st == 0 ? 3 : st);   // TIMEOUT fixup
        out[NN + 1] = (float)g_steps;
    }
}

extern "C" void kernel_launch(void* const* d_in, const int* in_sizes, int n_in,
                              void* d_out, int out_size) {
    const float* R  = (const float*)d_in[0];
    const float* sv = (const float*)d_in[1];
    float* out = (float*)d_out;

    init_kernel<<<32, 256>>>(sv);
    for (int k = 1; k <= MAXS; k++) {
        int pi  = (k - 1) % 3;   // prev
        int ppi = (k + 1) % 3;   // pprev  ((k-2) mod 3, kept non-negative)
        int ni  = k % 3;         // next
        gemv_step<<<1024, 256>>>(R, pi, ppi, ni);
        update_step<<<1, 1>>>(k, ni);
    }
    final_kernel<<<32, 256>>>(out, out_size);
}